// round 9
// baseline (speedup 1.0000x reference)
#include <cuda_runtime.h>
#include <cuda_fp16.h>

#define BB 64
#define II 4096
#define CC 32
#define DD 16
#define KD 16

#define NI 16                 // i's per fused CTA
#define NCH2 (II / NI)        // 256 chunks

#define WCH1H 4098            // Wf chunk1 base (halves): word 2049 == 1 mod 32
#define XQ1H  130             // xf chunk1 base (halves): word 65   == 1 mod 32

// Scratch (static device globals; no runtime allocation)
__device__ float g_spart2[(size_t)NCH2 * BB * 512];   // 33.5 MB: [chunk][row64][col512]
__device__ float g_spart3[8][BB * 512];               // 1 MB stage-1 partials
__device__ float g_V[BB * CC * DD];                   // Vsum, layout [b][c][D] == [b][n]

__global__ void dummy_kernel() {}

// ============================================================================
// Fused routing pass, quarter-M geometry:
// CTA = (chunk, bq): 256 threads = 8 warps; covers 16 b-rows x 512 n, NI i's.
// warp ng (0..7): cols 64*ng + 8*nt + 2*lc (8 n-tiles), rows lr and lr+8 (all 16).
// u recomputed via m16n8k16 fp16 mma; logits vs V -> softmax over 32 caps ->
// s accumulated in registers, one partial flush per CTA.
// ============================================================================

#define LOAD_REGS(ii)                                                           \
    {                                                                           \
        const float4* w4 = (const float4*)(w + (size_t)(ii) * 8192);            \
        _Pragma("unroll")                                                       \
        for (int q = 0; q < 8; q++) wreg[q] = w4[tid + q * 256];                \
        if (tid < 64) {                                                         \
            int row = tid >> 2;                                                 \
            xreg = *(const float4*)(x + ((size_t)(b_base + row) * II + (ii)) * KD \
                                    + (tid & 3) * 4);                           \
        }                                                                       \
    }

#define FILL_SMEM_FROM_REGS()                                                   \
    {                                                                           \
        _Pragma("unroll")                                                       \
        for (int q = 0; q < 8; q++) {                                           \
            int slot = tid + q * 256;                                           \
            int n = slot >> 2, d0 = (slot & 3) * 4;                             \
            int base = (d0 >= 8 ? WCH1H : 0) + n * 8 + (d0 & 7);                \
            *(__half2*)&Wf[base]     = __floats2half2_rn(wreg[q].x, wreg[q].y); \
            *(__half2*)&Wf[base + 2] = __floats2half2_rn(wreg[q].z, wreg[q].w); \
        }                                                                       \
        if (tid < 64) {                                                         \
            int row = tid >> 2, d0 = (tid & 3) * 4;                             \
            int base = (d0 >= 8 ? XQ1H : 0) + row * 8 + (d0 & 7);               \
            *(__half2*)&xf[base]     = __floats2half2_rn(xreg.x, xreg.y);       \
            *(__half2*)&xf[base + 2] = __floats2half2_rn(xreg.z, xreg.w);       \
        }                                                                       \
    }

#define DO_MMA(cdst)                                                            \
    {                                                                           \
        unsigned a0 = *(unsigned*)&xf[lr * 8 + 2 * lc];                         \
        unsigned a1 = *(unsigned*)&xf[(lr + 8) * 8 + 2 * lc];                   \
        unsigned a2 = *(unsigned*)&xf[XQ1H + lr * 8 + 2 * lc];                  \
        unsigned a3 = *(unsigned*)&xf[XQ1H + (lr + 8) * 8 + 2 * lc];            \
        _Pragma("unroll")                                                       \
        for (int nt = 0; nt < 8; nt++) {                                        \
            int nn = 64 * ng + 8 * nt + lr;                                     \
            unsigned b0 = *(unsigned*)&Wf[nn * 8 + 2 * lc];                     \
            unsigned b1 = *(unsigned*)&Wf[WCH1H + nn * 8 + 2 * lc];             \
            asm volatile(                                                       \
                "mma.sync.aligned.m16n8k16.row.col.f32.f16.f16.f32 "            \
                "{%0,%1,%2,%3}, {%4,%5,%6,%7}, {%8,%9}, {%0,%1,%2,%3};"         \
                : "+f"(cdst[nt][0]), "+f"(cdst[nt][1]),                         \
                  "+f"(cdst[nt][2]), "+f"(cdst[nt][3])                          \
                : "r"(a0), "r"(a1), "r"(a2), "r"(a3), "r"(b0), "r"(b1));        \
        }                                                                       \
    }

#define FLUSH_PARTIALS(src, scale)                                              \
    {                                                                           \
        float* dst = g_spart2 + (size_t)chunk * (BB * 512);                     \
        _Pragma("unroll")                                                       \
        for (int nt = 0; nt < 8; nt++) {                                        \
            int col = 64 * ng + 8 * nt + 2 * lc;                                \
            _Pragma("unroll")                                                   \
            for (int rp = 0; rp < 2; rp++) {                                    \
                int rowg = b_base + lr + 8 * rp;                                \
                float2 v2 = make_float2(src[nt][rp * 2] * (scale),              \
                                        src[nt][rp * 2 + 1] * (scale));         \
                *(float2*)&dst[rowg * 512 + col] = v2;                          \
            }                                                                   \
        }                                                                       \
    }

// ---------- pass 0: cij = 1/32 uniform; mma accumulates across i directly ----------
__global__ __launch_bounds__(256, 2) void fused_pass0(
    const float* __restrict__ x, const float* __restrict__ w) {
    __shared__ __half Wf[WCH1H + 4096];   // 512n x 16d fp16, chunked
    __shared__ __half xf[XQ1H + 128];     // 16b  x 16d fp16, chunked

    const int tid    = threadIdx.x;
    const int chunk  = blockIdx.x >> 2;
    const int bq     = blockIdx.x & 3;
    const int b_base = bq * 16;
    const int i0     = chunk * NI;
    const int l      = tid & 31;
    const int lr     = l >> 2, lc = l & 3;
    const int ng     = tid >> 5;

    float4 wreg[8];
    float4 xreg;

    float sacc[8][4];
    #pragma unroll
    for (int nt = 0; nt < 8; nt++)
        { sacc[nt][0] = 0.f; sacc[nt][1] = 0.f; sacc[nt][2] = 0.f; sacc[nt][3] = 0.f; }

    for (int j = 0; j < NI; j++) {
        LOAD_REGS(i0 + j);
        FILL_SMEM_FROM_REGS();
        __syncthreads();                   // smem ready
        DO_MMA(sacc);                      // s1 = sum_i u (accumulate in fragments)
        __syncthreads();                   // mma reads done before next fill
    }
    FLUSH_PARTIALS(sacc, (1.0f / 32.0f));
}

// ---------- pass 1/2: full softmax routing against V ----------
__global__ __launch_bounds__(256, 2) void fused_pass12(
    const float* __restrict__ x, const float* __restrict__ w) {
    __shared__ __half Wf[WCH1H + 4096];
    __shared__ __half xf[XQ1H + 128];
    __shared__ float  Lg[16 * 33];    // logits [row16][cap32], pitch 33
    __shared__ float  Cij[16 * 33];   // softmax weights

    const int tid    = threadIdx.x;
    const int chunk  = blockIdx.x >> 2;
    const int bq     = blockIdx.x & 3;
    const int b_base = bq * 16;
    const int i0     = chunk * NI;
    const int l      = tid & 31;
    const int lr     = l >> 2, lc = l & 3;
    const int ng     = tid >> 5;

    // V fragments: Vr[rp][k][ntp] = V[b(rp), cap=4ng+k, D=ntp*8+2lc+{0,1}]  (16 regs)
    __half2 Vr[2][4][2];
    #pragma unroll
    for (int rp = 0; rp < 2; rp++) {
        int b = b_base + lr + 8 * rp;
        #pragma unroll
        for (int k = 0; k < 4; k++) {
            int cg = 4 * ng + k;
            #pragma unroll
            for (int ntp = 0; ntp < 2; ntp++) {
                float2 vv = *(const float2*)&g_V[((b * CC + cg) << 4) + ntp * 8 + 2 * lc];
                Vr[rp][k][ntp] = __floats2half2_rn(vv.x, vv.y);
            }
        }
    }

    float4 wreg[8];
    float4 xreg;

    float sacc[8][4];
    #pragma unroll
    for (int nt = 0; nt < 8; nt++)
        { sacc[nt][0] = 0.f; sacc[nt][1] = 0.f; sacc[nt][2] = 0.f; sacc[nt][3] = 0.f; }

    for (int j = 0; j < NI; j++) {
        LOAD_REGS(i0 + j);
        FILL_SMEM_FROM_REGS();
        __syncthreads();                   // A: smem ready

        float cacc[8][4];
        #pragma unroll
        for (int nt = 0; nt < 8; nt++)
            { cacc[nt][0] = 0.f; cacc[nt][1] = 0.f; cacc[nt][2] = 0.f; cacc[nt][3] = 0.f; }
        DO_MMA(cacc);

        // logit partials over this thread's 4 D-slots per cap, then quad-reduce
        float p[2][4];
        #pragma unroll
        for (int rp = 0; rp < 2; rp++) {
            #pragma unroll
            for (int k = 0; k < 4; k++) {
                float pr = 0.0f;
                #pragma unroll
                for (int ntp = 0; ntp < 2; ntp++) {
                    float2 vv = __half22float2(Vr[rp][k][ntp]);
                    int nt = 2 * k + ntp;
                    pr = fmaf(cacc[nt][rp * 2],     vv.x, pr);
                    pr = fmaf(cacc[nt][rp * 2 + 1], vv.y, pr);
                }
                p[rp][k] = pr;
            }
        }
        #pragma unroll
        for (int rp = 0; rp < 2; rp++)
            #pragma unroll
            for (int k = 0; k < 4; k++) {
                p[rp][k] += __shfl_xor_sync(0xffffffffu, p[rp][k], 1);
                p[rp][k] += __shfl_xor_sync(0xffffffffu, p[rp][k], 2);
            }
        if (lc == 0) {
            #pragma unroll
            for (int rp = 0; rp < 2; rp++) {
                int row = lr + 8 * rp;
                #pragma unroll
                for (int k = 0; k < 4; k++)
                    Lg[row * 33 + 4 * ng + k] = p[rp][k];
            }
        }
        __syncthreads();                   // B: logits complete

        // softmax over 32 caps: 64 threads, thread = (row, 8-cap slice)
        if (tid < 64) {
            int row = tid >> 2, c0 = (tid & 3) * 8;
            float lv[8];
            float m = -1e30f;
            #pragma unroll
            for (int k = 0; k < 8; k++) {
                lv[k] = Lg[row * 33 + c0 + k];
                m = fmaxf(m, lv[k]);
            }
            m = fmaxf(m, __shfl_xor_sync(0xffffffffu, m, 1));
            m = fmaxf(m, __shfl_xor_sync(0xffffffffu, m, 2));
            float sum = 0.0f;
            #pragma unroll
            for (int k = 0; k < 8; k++) { lv[k] = __expf(lv[k] - m); sum += lv[k]; }
            sum += __shfl_xor_sync(0xffffffffu, sum, 1);
            sum += __shfl_xor_sync(0xffffffffu, sum, 2);
            float inv = 1.0f / sum;
            #pragma unroll
            for (int k = 0; k < 8; k++) Cij[row * 33 + c0 + k] = lv[k] * inv;
        }
        __syncthreads();                   // C: Cij ready (also guards smem reuse)

        // s += cij * u
        #pragma unroll
        for (int nt = 0; nt < 8; nt++) {
            int cap = 4 * ng + (nt >> 1);
            #pragma unroll
            for (int rp = 0; rp < 2; rp++) {
                float cij = Cij[(lr + 8 * rp) * 33 + cap];
                sacc[nt][rp * 2]     = fmaf(cij, cacc[nt][rp * 2],     sacc[nt][rp * 2]);
                sacc[nt][rp * 2 + 1] = fmaf(cij, cacc[nt][rp * 2 + 1], sacc[nt][rp * 2 + 1]);
            }
        }
    }
    FLUSH_PARTIALS(sacc, 1.0f);
}

// ---------- stage 1: 256 chunks -> 8 partials, fully parallel/coalesced ----------
__global__ void reduce_stage1() {
    int gid = blockIdx.x * blockDim.x + threadIdx.x;   // 0..262143
    int g = gid >> 15, t = gid & 32767;
    float s = 0.0f;
    #pragma unroll 8
    for (int ch = 0; ch < 32; ch++)
        s += g_spart2[(size_t)(g * 32 + ch) * (BB * 512) + t];
    g_spart3[g][t] = s;
}

// ---------- stage 2: sum 8 partials + squash; thread per (b, n) ----------
__global__ void reduce_stage2(float* __restrict__ out, int pass) {
    int t = blockIdx.x * blockDim.x + threadIdx.x;
    float s = 0.0f;
    #pragma unroll
    for (int g = 0; g < 8; g++) s += g_spart3[g][t];

    float sq = s * s;
    #pragma unroll
    for (int off = 1; off < 16; off <<= 1)
        sq += __shfl_xor_sync(0xffffffffu, sq, off);   // sums the capsule's 16 D's

    float f = 1.0f / ((1.0f + sq) * sqrtf(sq + 1e-9f));
    float v = s * f;

    if (pass == 0)      g_V[t] = v;
    else if (pass == 1) g_V[t] += v;
    else                out[t] = v;
}

extern "C" void kernel_launch(void* const* d_in, const int* in_sizes, int n_in,
                              void* d_out, int out_size) {
    const float* x = (const float*)d_in[0];
    const float* w = (const float*)d_in[1];
    float* out = (float*)d_out;

    // two dummies put fused_pass12 at launch #6 for the ncu -s 5 -c 1 window
    dummy_kernel<<<1, 32>>>();
    dummy_kernel<<<1, 32>>>();

    fused_pass0<<<NCH2 * 4, 256>>>(x, w);
    reduce_stage1<<<1024, 256>>>();
    reduce_stage2<<<128, 256>>>(out, 0);

    fused_pass12<<<NCH2 * 4, 256>>>(x, w);
    reduce_stage1<<<1024, 256>>>();
    reduce_stage2<<<128, 256>>>(out, 1);

    fused_pass12<<<NCH2 * 4, 256>>>(x, w);
    reduce_stage1<<<1024, 256>>>();
    reduce_stage2<<<128, 256>>>(out, 2);
}

// round 10
// speedup vs baseline: 1.0283x; 1.0283x over previous
#include <cuda_runtime.h>
#include <cuda_fp16.h>

#define BB 64
#define II 4096
#define CC 32
#define DD 16
#define KD 16

#define NI 64                 // i's per fused CTA
#define NCH2 (II / NI)        // 64 chunks

#define WCH1H 4098            // Wf chunk1 base (halves): word 2049 == 1 mod 32
#define XQ1H  130             // xf chunk1 base (halves): word 65   == 1 mod 32
#define VPH   520             // Vsm pitch (halves): 260 words == 4 mod 32

// Scratch (static device globals; no runtime allocation)
__device__ float g_spart2[(size_t)NCH2 * BB * 512];   // 8.4 MB: [chunk][row64][col512]
__device__ float g_spart3[8][BB * 512];               // 1 MB stage-1 partials
__device__ float g_V[BB * CC * DD];                   // Vsum, layout [b][n], n = c*16+D

__global__ void dummy_kernel() {}

// ============================================================================
// Fused routing pass, quarter-M geometry + prefetch:
// CTA = (chunk, bq): 256 threads = 8 warps; 16 b-rows x 512 n, NI=64 i's.
// warp ng (0..7): cols 64*ng + 8*nt + 2*lc (8 n-tiles), rows lr, lr+8.
// u recomputed via m16n8k16 fp16 mma; logits vs V (smem) -> softmax(32 caps)
// -> s accumulated in registers; one partial flush per CTA.
// ============================================================================

#define LOAD_REGS(ii)                                                           \
    {                                                                           \
        const float4* w4 = (const float4*)(w + (size_t)(ii) * 8192);            \
        _Pragma("unroll")                                                       \
        for (int q = 0; q < 8; q++) wreg[q] = w4[tid + q * 256];                \
        if (tid < 64) {                                                         \
            int row = tid >> 2;                                                 \
            xreg = *(const float4*)(x + ((size_t)(b_base + row) * II + (ii)) * KD \
                                    + (tid & 3) * 4);                           \
        }                                                                       \
    }

#define FILL_SMEM_FROM_REGS()                                                   \
    {                                                                           \
        _Pragma("unroll")                                                       \
        for (int q = 0; q < 8; q++) {                                           \
            int slot = tid + q * 256;                                           \
            int n = slot >> 2, d0 = (slot & 3) * 4;                             \
            int base = (d0 >= 8 ? WCH1H : 0) + n * 8 + (d0 & 7);                \
            *(__half2*)&Wf[base]     = __floats2half2_rn(wreg[q].x, wreg[q].y); \
            *(__half2*)&Wf[base + 2] = __floats2half2_rn(wreg[q].z, wreg[q].w); \
        }                                                                       \
        if (tid < 64) {                                                         \
            int row = tid >> 2, d0 = (tid & 3) * 4;                             \
            int base = (d0 >= 8 ? XQ1H : 0) + row * 8 + (d0 & 7);               \
            *(__half2*)&xf[base]     = __floats2half2_rn(xreg.x, xreg.y);       \
            *(__half2*)&xf[base + 2] = __floats2half2_rn(xreg.z, xreg.w);       \
        }                                                                       \
    }

#define DO_MMA(cdst)                                                            \
    {                                                                           \
        unsigned a0 = *(unsigned*)&xf[lr * 8 + 2 * lc];                         \
        unsigned a1 = *(unsigned*)&xf[(lr + 8) * 8 + 2 * lc];                   \
        unsigned a2 = *(unsigned*)&xf[XQ1H + lr * 8 + 2 * lc];                  \
        unsigned a3 = *(unsigned*)&xf[XQ1H + (lr + 8) * 8 + 2 * lc];            \
        _Pragma("unroll")                                                       \
        for (int nt = 0; nt < 8; nt++) {                                        \
            int nn = 64 * ng + 8 * nt + lr;                                     \
            unsigned b0 = *(unsigned*)&Wf[nn * 8 + 2 * lc];                     \
            unsigned b1 = *(unsigned*)&Wf[WCH1H + nn * 8 + 2 * lc];             \
            asm volatile(                                                       \
                "mma.sync.aligned.m16n8k16.row.col.f32.f16.f16.f32 "            \
                "{%0,%1,%2,%3}, {%4,%5,%6,%7}, {%8,%9}, {%0,%1,%2,%3};"         \
                : "+f"(cdst[nt][0]), "+f"(cdst[nt][1]),                         \
                  "+f"(cdst[nt][2]), "+f"(cdst[nt][3])                          \
                : "r"(a0), "r"(a1), "r"(a2), "r"(a3), "r"(b0), "r"(b1));        \
        }                                                                       \
    }

#define FLUSH_PARTIALS(src, scale)                                              \
    {                                                                           \
        float* dst = g_spart2 + (size_t)chunk * (BB * 512);                     \
        _Pragma("unroll")                                                       \
        for (int nt = 0; nt < 8; nt++) {                                        \
            int col = 64 * ng + 8 * nt + 2 * lc;                                \
            _Pragma("unroll")                                                   \
            for (int rp = 0; rp < 2; rp++) {                                    \
                int rowg = b_base + lr + 8 * rp;                                \
                float2 v2 = make_float2(src[nt][rp * 2] * (scale),              \
                                        src[nt][rp * 2 + 1] * (scale));         \
                *(float2*)&dst[rowg * 512 + col] = v2;                          \
            }                                                                   \
        }                                                                       \
    }

// ---------- pass 0: cij = 1/32 uniform; mma accumulates across i directly ----------
__global__ __launch_bounds__(256, 2) void fused_pass0(
    const float* __restrict__ x, const float* __restrict__ w) {
    __shared__ __half Wf[WCH1H + 4096];   // 512n x 16d fp16, chunked
    __shared__ __half xf[XQ1H + 128];     // 16b  x 16d fp16, chunked

    const int tid    = threadIdx.x;
    const int chunk  = blockIdx.x >> 2;
    const int bq     = blockIdx.x & 3;
    const int b_base = bq * 16;
    const int i0     = chunk * NI;
    const int l      = tid & 31;
    const int lr     = l >> 2, lc = l & 3;
    const int ng     = tid >> 5;

    float4 wreg[8];
    float4 xreg;
    LOAD_REGS(i0);

    float sacc[8][4];
    #pragma unroll
    for (int nt = 0; nt < 8; nt++)
        { sacc[nt][0] = 0.f; sacc[nt][1] = 0.f; sacc[nt][2] = 0.f; sacc[nt][3] = 0.f; }

    for (int j = 0; j < NI; j++) {
        FILL_SMEM_FROM_REGS();
        __syncthreads();                       // smem ready
        if (j + 1 < NI) LOAD_REGS(i0 + j + 1); // prefetch overlaps mma
        DO_MMA(sacc);                          // s1 = sum_i u
        __syncthreads();                       // mma reads done before next fill
    }
    FLUSH_PARTIALS(sacc, (1.0f / 32.0f));
}

// ---------- pass 1/2: full softmax routing against V (V in smem) ----------
__global__ __launch_bounds__(256, 2) void fused_pass12(
    const float* __restrict__ x, const float* __restrict__ w) {
    __shared__ __half Wf[WCH1H + 4096];
    __shared__ __half xf[XQ1H + 128];
    __shared__ __half Vsm[16 * VPH];  // V rows for this b-quarter, pitch 520
    __shared__ float  Lg[16 * 33];    // logits [row16][cap32], pitch 33
    __shared__ float  Cij[16 * 33];   // softmax weights

    const int tid    = threadIdx.x;
    const int chunk  = blockIdx.x >> 2;
    const int bq     = blockIdx.x & 3;
    const int b_base = bq * 16;
    const int i0     = chunk * NI;
    const int l      = tid & 31;
    const int lr     = l >> 2, lc = l & 3;
    const int ng     = tid >> 5;

    // load V tile (16 rows x 512) into smem as fp16
    for (int e = tid; e < 16 * 512; e += 256) {
        int row = e >> 9, n = e & 511;
        Vsm[row * VPH + n] = __float2half(g_V[(size_t)(b_base + row) * 512 + n]);
    }

    float4 wreg[8];
    float4 xreg;
    LOAD_REGS(i0);

    float sacc[8][4];
    #pragma unroll
    for (int nt = 0; nt < 8; nt++)
        { sacc[nt][0] = 0.f; sacc[nt][1] = 0.f; sacc[nt][2] = 0.f; sacc[nt][3] = 0.f; }

    __syncthreads();   // Vsm ready (also covers first fill ordering below)

    for (int j = 0; j < NI; j++) {
        FILL_SMEM_FROM_REGS();
        __syncthreads();                       // A: smem ready
        if (j + 1 < NI) LOAD_REGS(i0 + j + 1); // prefetch overlaps mma+softmax

        float cacc[8][4];
        #pragma unroll
        for (int nt = 0; nt < 8; nt++)
            { cacc[nt][0] = 0.f; cacc[nt][1] = 0.f; cacc[nt][2] = 0.f; cacc[nt][3] = 0.f; }
        DO_MMA(cacc);

        // logit partials vs Vsm (conflict-free LDS), then quad-reduce
        float p[2][4];
        #pragma unroll
        for (int rp = 0; rp < 2; rp++) {
            int row = lr + 8 * rp;
            #pragma unroll
            for (int k = 0; k < 4; k++) {
                int cap = 4 * ng + k;
                float pr = 0.0f;
                #pragma unroll
                for (int ntp = 0; ntp < 2; ntp++) {
                    __half2 vh = *(__half2*)&Vsm[row * VPH + cap * 16 + ntp * 8 + 2 * lc];
                    float2 vv = __half22float2(vh);
                    int nt = 2 * k + ntp;
                    pr = fmaf(cacc[nt][rp * 2],     vv.x, pr);
                    pr = fmaf(cacc[nt][rp * 2 + 1], vv.y, pr);
                }
                p[rp][k] = pr;
            }
        }
        #pragma unroll
        for (int rp = 0; rp < 2; rp++)
            #pragma unroll
            for (int k = 0; k < 4; k++) {
                p[rp][k] += __shfl_xor_sync(0xffffffffu, p[rp][k], 1);
                p[rp][k] += __shfl_xor_sync(0xffffffffu, p[rp][k], 2);
            }
        if (lc == 0) {
            #pragma unroll
            for (int rp = 0; rp < 2; rp++) {
                int row = lr + 8 * rp;
                #pragma unroll
                for (int k = 0; k < 4; k++)
                    Lg[row * 33 + 4 * ng + k] = p[rp][k];
            }
        }
        __syncthreads();                       // B: logits complete

        // softmax over 32 caps: 64 threads, thread = (row, 8-cap slice)
        if (tid < 64) {
            int row = tid >> 2, c0 = (tid & 3) * 8;
            float lv[8];
            float m = -1e30f;
            #pragma unroll
            for (int k = 0; k < 8; k++) {
                lv[k] = Lg[row * 33 + c0 + k];
                m = fmaxf(m, lv[k]);
            }
            m = fmaxf(m, __shfl_xor_sync(0xffffffffu, m, 1));
            m = fmaxf(m, __shfl_xor_sync(0xffffffffu, m, 2));
            float sum = 0.0f;
            #pragma unroll
            for (int k = 0; k < 8; k++) { lv[k] = __expf(lv[k] - m); sum += lv[k]; }
            sum += __shfl_xor_sync(0xffffffffu, sum, 1);
            sum += __shfl_xor_sync(0xffffffffu, sum, 2);
            float inv = 1.0f / sum;
            #pragma unroll
            for (int k = 0; k < 8; k++) Cij[row * 33 + c0 + k] = lv[k] * inv;
        }
        __syncthreads();                       // C: Cij ready (guards smem reuse)

        // s += cij * u
        #pragma unroll
        for (int nt = 0; nt < 8; nt++) {
            int cap = 4 * ng + (nt >> 1);
            #pragma unroll
            for (int rp = 0; rp < 2; rp++) {
                float cij = Cij[(lr + 8 * rp) * 33 + cap];
                sacc[nt][rp * 2]     = fmaf(cij, cacc[nt][rp * 2],     sacc[nt][rp * 2]);
                sacc[nt][rp * 2 + 1] = fmaf(cij, cacc[nt][rp * 2 + 1], sacc[nt][rp * 2 + 1]);
            }
        }
    }
    FLUSH_PARTIALS(sacc, 1.0f);
}

// ---------- stage 1: 64 chunks -> 8 partials, fully parallel/coalesced ----------
__global__ void reduce_stage1() {
    int gid = blockIdx.x * blockDim.x + threadIdx.x;   // 0..262143
    int g = gid >> 15, t = gid & 32767;
    float s = 0.0f;
    #pragma unroll
    for (int ch = 0; ch < NCH2 / 8; ch++)
        s += g_spart2[(size_t)(g * (NCH2 / 8) + ch) * (BB * 512) + t];
    g_spart3[g][t] = s;
}

// ---------- stage 2: sum 8 partials + squash; thread per (b, n) ----------
__global__ void reduce_stage2(float* __restrict__ out, int pass) {
    int t = blockIdx.x * blockDim.x + threadIdx.x;
    float s = 0.0f;
    #pragma unroll
    for (int g = 0; g < 8; g++) s += g_spart3[g][t];

    float sq = s * s;
    #pragma unroll
    for (int off = 1; off < 16; off <<= 1)
        sq += __shfl_xor_sync(0xffffffffu, sq, off);   // sums the capsule's 16 D's

    float f = 1.0f / ((1.0f + sq) * sqrtf(sq + 1e-9f));
    float v = s * f;

    if (pass == 0)      g_V[t] = v;
    else if (pass == 1) g_V[t] += v;
    else                out[t] = v;
}

extern "C" void kernel_launch(void* const* d_in, const int* in_sizes, int n_in,
                              void* d_out, int out_size) {
    const float* x = (const float*)d_in[0];
    const float* w = (const float*)d_in[1];
    float* out = (float*)d_out;

    // two dummies put fused_pass12 at launch #6 for the ncu -s 5 -c 1 window
    dummy_kernel<<<1, 32>>>();
    dummy_kernel<<<1, 32>>>();

    fused_pass0<<<NCH2 * 4, 256>>>(x, w);
    reduce_stage1<<<1024, 256>>>();
    reduce_stage2<<<128, 256>>>(out, 0);

    fused_pass12<<<NCH2 * 4, 256>>>(x, w);
    reduce_stage1<<<1024, 256>>>();
    reduce_stage2<<<128, 256>>>(out, 1);

    fused_pass12<<<NCH2 * 4, 256>>>(x, w);
    reduce_stage1<<<1024, 256>>>();
    reduce_stage2<<<128, 256>>>(out, 2);
}

// round 11
// speedup vs baseline: 1.1038x; 1.0734x over previous
#include <cuda_runtime.h>
#include <cuda_fp16.h>

#define BB 64
#define II 4096
#define CC 32
#define DD 16
#define KD 16

#define NCHUNK 32      // i-chunks for routing partials
#define RITERS 16      // i's per warp per routing CTA: NCHUNK*8*RITERS == II

#define WQ1H 544       // Wf chunk1 base (halves): word 272 == 16 mod 32
#define XQ1H 544       // xf chunk1 base (halves): word 272 == 16 mod 32
#define OPH2 72        // Osm pitch (halves): 36 words == 4 mod 32

// Scratch (static device globals; no runtime allocation)
__device__ __half g_uhat[(size_t)BB * II * CC * DD];   // 268 MB, layout [b][i][n=c*16+D]
__device__ float  g_spart[NCHUNK][BB * CC * DD];       // partial s, layout [chunk][b][D][c]
__device__ float  g_V[BB * CC * DD];                   // Vsum, layout [b][c][D]

// ---------- pass 0 (fp16 tensor cores, v6): small CTAs for occupancy ----------
// CTA = (i, e): 128 threads = 4 warps; covers all 64 b x 64 n (n-eighth e).
// warp w = b-rowtile 16w..16w+15, loops 8 n-tiles. m16n8k16 fp16 mma, fp32 acc.
// Per-warp epilogue staging (own rows only) -> __syncwarp -> coalesced STG.128.
__global__ __launch_bounds__(128) void uhat_kernel(
    const float* __restrict__ x, const float* __restrict__ w) {
    __shared__ __half Wf[WQ1H + 512];   // 64n x 16d fp16, chunked by k-half
    __shared__ __half xf[XQ1H + 512];   // 64b x 16d fp16, chunked by k-half
    __shared__ __half Osm[BB * OPH2];   // [b*72 + n_local]

    const int tid = threadIdx.x;
    const int i   = blockIdx.x >> 3;
    const int e   = blockIdx.x & 7;      // n-eighth: global cols 64e .. 64e+63
    const int wp  = tid >> 5;            // warp = mt (row tile)
    const int l   = tid & 31;
    const int lr  = l >> 2, lc = l & 3;

    // ---- fill: W slab (64n x 16d) and x tile (64b x 16d), f32 -> f16, chunked ----
    {
        const float4* w4 = (const float4*)(w + (size_t)i * 8192 + e * 1024);
        #pragma unroll
        for (int q = 0; q < 2; q++) {
            int slot = tid + q * 128;             // 256 float4 slots
            int n = slot >> 2, d0 = (slot & 3) * 4;
            float4 v = w4[slot];
            int base = (d0 >= 8 ? WQ1H : 0) + n * 8 + (d0 & 7);
            *(__half2*)&Wf[base]     = __floats2half2_rn(v.x, v.y);
            *(__half2*)&Wf[base + 2] = __floats2half2_rn(v.z, v.w);
        }
        #pragma unroll
        for (int q = 0; q < 2; q++) {
            int slot = tid + q * 128;
            int b = slot >> 2, d0 = (slot & 3) * 4;
            float4 v = *(const float4*)(x + ((size_t)b * II + i) * KD + d0);
            int base = (d0 >= 8 ? XQ1H : 0) + b * 8 + (d0 & 7);
            *(__half2*)&xf[base]     = __floats2half2_rn(v.x, v.y);
            *(__half2*)&xf[base + 2] = __floats2half2_rn(v.z, v.w);
        }
    }
    __syncthreads();

    // ---- A fragments (rows 16wp+lr, +8; k split in chunks) ----
    unsigned a0, a1, a2, a3;
    {
        int r = 16 * wp + lr;
        a0 = *(unsigned*)&xf[r * 8 + 2 * lc];
        a1 = *(unsigned*)&xf[(r + 8) * 8 + 2 * lc];
        a2 = *(unsigned*)&xf[XQ1H + r * 8 + 2 * lc];
        a3 = *(unsigned*)&xf[XQ1H + (r + 8) * 8 + 2 * lc];
    }

    // ---- mma: 8 n-tiles, one m16n8k16 each ----
    float c[8][4];
    #pragma unroll
    for (int nt = 0; nt < 8; nt++)
        { c[nt][0] = 0.f; c[nt][1] = 0.f; c[nt][2] = 0.f; c[nt][3] = 0.f; }

    #pragma unroll
    for (int nt = 0; nt < 8; nt++) {
        int nn = 8 * nt + lr;
        unsigned b0 = *(unsigned*)&Wf[nn * 8 + 2 * lc];
        unsigned b1 = *(unsigned*)&Wf[WQ1H + nn * 8 + 2 * lc];
        asm volatile(
            "mma.sync.aligned.m16n8k16.row.col.f32.f16.f16.f32 "
            "{%0,%1,%2,%3}, {%4,%5,%6,%7}, {%8,%9}, {%0,%1,%2,%3};"
            : "+f"(c[nt][0]), "+f"(c[nt][1]), "+f"(c[nt][2]), "+f"(c[nt][3])
            : "r"(a0), "r"(a1), "r"(a2), "r"(a3), "r"(b0), "r"(b1));
    }

    // ---- epilogue: fragments -> Osm rows 16wp..16wp+15 (own-warp only) ----
    {
        int r0 = 16 * wp + lr, r1 = r0 + 8;
        #pragma unroll
        for (int nt = 0; nt < 8; nt++) {
            int col = 8 * nt + 2 * lc;
            *(__half2*)&Osm[r0 * OPH2 + col] = __floats2half2_rn(c[nt][0], c[nt][1]);
            *(__half2*)&Osm[r1 * OPH2 + col] = __floats2half2_rn(c[nt][2], c[nt][3]);
        }
    }
    __syncwarp();   // warp reads only its own rows below

    // ---- store: 4 iters; per iter the warp stores 4 rows x 128B contiguous ----
    {
        const int rsub = l >> 3;           // 0..3
        const int colh = (l & 7) * 8;      // 0..56 halves
        #pragma unroll
        for (int r = 0; r < 4; r++) {
            int b = 16 * wp + 4 * r + rsub;
            uint4 v = *(uint4*)&Osm[b * OPH2 + colh];
            *(uint4*)(g_uhat + ((size_t)b * II + i) * (CC * DD) + 64 * e + colh) = v;
        }
    }
}

// ---------- routing pass: s[b,c,D] = sum_i softmax_c(u . Vsum) * u ----------
__global__ __launch_bounds__(256) void routing_kernel(int pass1) {
    const int b     = blockIdx.y;
    const int chunk = blockIdx.x;
    const int warp  = threadIdx.x >> 5;
    const int c     = threadIdx.x & 31;

    float V[DD];
    if (!pass1) {
        #pragma unroll
        for (int D = 0; D < DD; D++) V[D] = g_V[(b * CC + c) * DD + D];
    }

    float sacc[DD];
    #pragma unroll
    for (int D = 0; D < DD; D++) sacc[D] = 0.0f;

    const int i0 = chunk * (8 * RITERS) + warp * RITERS;
    const uint4* p = (const uint4*)(g_uhat + ((size_t)b * II + i0) * (CC * DD)) + c * 2;

    uint4 q0 = p[0];
    uint4 q1 = p[1];

    #pragma unroll 4
    for (int k = 0; k < RITERS; k++) {
        uint4 n0 = q0, n1 = q1;
        if (k + 1 < RITERS) {
            n0 = p[(k + 1) * 64];
            n1 = p[(k + 1) * 64 + 1];
        }

        float u[DD];
        unsigned rr[8] = {q0.x, q0.y, q0.z, q0.w, q1.x, q1.y, q1.z, q1.w};
        #pragma unroll
        for (int pp = 0; pp < 8; pp++) {
            __half2 h = *reinterpret_cast<__half2*>(&rr[pp]);
            float2 f = __half22float2(h);
            u[2 * pp]     = f.x;
            u[2 * pp + 1] = f.y;
        }

        float cij;
        if (pass1) {
            cij = 1.0f / 32.0f;
        } else {
            float logit = 0.0f;
            #pragma unroll
            for (int D = 0; D < DD; D++) logit = fmaf(u[D], V[D], logit);
            float m = logit;
            #pragma unroll
            for (int off = 16; off > 0; off >>= 1)
                m = fmaxf(m, __shfl_xor_sync(0xffffffffu, m, off));
            float ev = __expf(logit - m);
            float ssum = ev;
            #pragma unroll
            for (int off = 16; off > 0; off >>= 1)
                ssum += __shfl_xor_sync(0xffffffffu, ssum, off);
            cij = ev / ssum;
        }

        #pragma unroll
        for (int D = 0; D < DD; D++) sacc[D] = fmaf(cij, u[D], sacc[D]);

        q0 = n0; q1 = n1;
    }

    __shared__ float red[8][CC * DD];
    #pragma unroll
    for (int D = 0; D < DD; D++) red[warp][D * 32 + c] = sacc[D];
    __syncthreads();

    for (int t = threadIdx.x; t < CC * DD; t += 256) {
        float v = 0.0f;
        #pragma unroll
        for (int wq = 0; wq < 8; wq++) v += red[wq][t];
        g_spart[chunk][b * (CC * DD) + t] = v;   // [chunk][b][D][c]
    }
}

// ---------- squash: one thread per (b,c,D); 16-lane shfl for |s|^2 ----------
__global__ void squash_kernel(float* __restrict__ out, int pass) {
    int t = blockIdx.x * blockDim.x + threadIdx.x;   // (b,c,D), D fastest
    int bc = t >> 4, D = t & 15;
    int b = bc >> 5, c = bc & 31;
    int addr = b * (CC * DD) + D * 32 + c;           // [b][D][c] partial layout

    float s = 0.0f;
    #pragma unroll
    for (int ch = 0; ch < NCHUNK; ch++) s += g_spart[ch][addr];

    float sq = s * s;
    #pragma unroll
    for (int off = 1; off < 16; off <<= 1)
        sq += __shfl_xor_sync(0xffffffffu, sq, off);

    float f = 1.0f / ((1.0f + sq) * sqrtf(sq + 1e-9f));
    float v = s * f;

    if (pass == 0)      g_V[t] = v;
    else if (pass == 1) g_V[t] += v;
    else                out[t] = v;
}

extern "C" void kernel_launch(void* const* d_in, const int* in_sizes, int n_in,
                              void* d_out, int out_size) {
    const float* x = (const float*)d_in[0];
    const float* w = (const float*)d_in[1];
    float* out = (float*)d_out;

    uhat_kernel<<<II * 8, 128>>>(x, w);

    routing_kernel<<<dim3(NCHUNK, BB), 256>>>(1);
    squash_kernel<<<128, 256>>>(out, 0);

    routing_kernel<<<dim3(NCHUNK, BB), 256>>>(0);
    squash_kernel<<<128, 256>>>(out, 1);

    routing_kernel<<<dim3(NCHUNK, BB), 256>>>(0);
    squash_kernel<<<128, 256>>>(out, 2);
}

// round 12
// speedup vs baseline: 1.1208x; 1.0154x over previous
#include <cuda_runtime.h>
#include <cuda_fp16.h>

#define BB 64
#define II 4096
#define CC 32
#define DD 16
#define KD 16

#define NCHUNK 32      // i-chunks for routing partials
#define RITERS 16      // i's per warp per routing CTA: NCHUNK*8*RITERS == II

#define NI1  32        // i's per uhat CTA
#define NCH1 (II/NI1)  // 128 s1-chunks

#define WQ1H 544       // Wf chunk1 base (halves): word 272 == 16 mod 32
#define XQ1H 544       // xf chunk1 base (halves)
#define OPH2 72        // Osm pitch (halves): 36 words == 4 mod 32

// Scratch (static device globals; no runtime allocation)
__device__ __half g_uhat[(size_t)BB * II * CC * DD];   // 268 MB, layout [b][i][n=c*16+D]
__device__ float  g_spart1[NCH1][BB * 512];            // 16.8 MB s1 partials [chunk][b][n]
__device__ float  g_spart3[8][BB * 512];               // 1 MB stage-1 partials
__device__ float  g_spart[NCHUNK][BB * CC * DD];       // routing partials [chunk][b][D][c]
__device__ float  g_V[BB * CC * DD];                   // Vsum, layout [b][n]

// ---------- pass 0 (fp16 tensor cores, v7): u_hat store + fused s1 accumulation ----
// CTA = (chunk of NI1 i's, e): 128 threads = 4 warps; 64 b x 64 n (n-eighth e).
// warp wp = b-rowtile 16wp..16wp+15. m16n8k16 fp16 mma, fp32 acc.
// Per i: fill -> mma -> s1acc += frags -> epilogue/store. One s1 flush per CTA.
__global__ __launch_bounds__(128) void uhat_kernel(
    const float* __restrict__ x, const float* __restrict__ w) {
    __shared__ __half Wf[WQ1H + 512];   // 64n x 16d fp16, chunked by k-half
    __shared__ __half xf[XQ1H + 512];   // 64b x 16d fp16, chunked by k-half
    __shared__ __half Osm[BB * OPH2];   // [b*72 + n_local]

    const int tid   = threadIdx.x;
    const int chunk = blockIdx.x >> 3;
    const int e     = blockIdx.x & 7;    // n-eighth: global cols 64e .. 64e+63
    const int wp    = tid >> 5;
    const int l     = tid & 31;
    const int lr    = l >> 2, lc = l & 3;
    const int rsub  = l >> 3;            // store-phase row-sub 0..3
    const int colh  = (l & 7) * 8;       // store-phase col (halves)

    float s1[8][4];
    #pragma unroll
    for (int nt = 0; nt < 8; nt++)
        { s1[nt][0] = 0.f; s1[nt][1] = 0.f; s1[nt][2] = 0.f; s1[nt][3] = 0.f; }

    for (int j = 0; j < NI1; j++) {
        const int i = chunk * NI1 + j;

        // ---- fill: W slab (64n x 16d) and x tile (64b x 16d), f32 -> f16 ----
        {
            const float4* w4 = (const float4*)(w + (size_t)i * 8192 + e * 1024);
            #pragma unroll
            for (int q = 0; q < 2; q++) {
                int slot = tid + q * 128;
                int n = slot >> 2, d0 = (slot & 3) * 4;
                float4 v = w4[slot];
                int base = (d0 >= 8 ? WQ1H : 0) + n * 8 + (d0 & 7);
                *(__half2*)&Wf[base]     = __floats2half2_rn(v.x, v.y);
                *(__half2*)&Wf[base + 2] = __floats2half2_rn(v.z, v.w);
            }
            #pragma unroll
            for (int q = 0; q < 2; q++) {
                int slot = tid + q * 128;
                int b = slot >> 2, d0 = (slot & 3) * 4;
                float4 v = *(const float4*)(x + ((size_t)b * II + i) * KD + d0);
                int base = (d0 >= 8 ? XQ1H : 0) + b * 8 + (d0 & 7);
                *(__half2*)&xf[base]     = __floats2half2_rn(v.x, v.y);
                *(__half2*)&xf[base + 2] = __floats2half2_rn(v.z, v.w);
            }
        }
        __syncthreads();

        // ---- fragments + mma: 8 n-tiles ----
        float cacc[8][4];
        #pragma unroll
        for (int nt = 0; nt < 8; nt++)
            { cacc[nt][0] = 0.f; cacc[nt][1] = 0.f; cacc[nt][2] = 0.f; cacc[nt][3] = 0.f; }
        {
            int r = 16 * wp + lr;
            unsigned a0 = *(unsigned*)&xf[r * 8 + 2 * lc];
            unsigned a1 = *(unsigned*)&xf[(r + 8) * 8 + 2 * lc];
            unsigned a2 = *(unsigned*)&xf[XQ1H + r * 8 + 2 * lc];
            unsigned a3 = *(unsigned*)&xf[XQ1H + (r + 8) * 8 + 2 * lc];
            #pragma unroll
            for (int nt = 0; nt < 8; nt++) {
                int nn = 8 * nt + lr;
                unsigned b0 = *(unsigned*)&Wf[nn * 8 + 2 * lc];
                unsigned b1 = *(unsigned*)&Wf[WQ1H + nn * 8 + 2 * lc];
                asm volatile(
                    "mma.sync.aligned.m16n8k16.row.col.f32.f16.f16.f32 "
                    "{%0,%1,%2,%3}, {%4,%5,%6,%7}, {%8,%9}, {%0,%1,%2,%3};"
                    : "+f"(cacc[nt][0]), "+f"(cacc[nt][1]),
                      "+f"(cacc[nt][2]), "+f"(cacc[nt][3])
                    : "r"(a0), "r"(a1), "r"(a2), "r"(a3), "r"(b0), "r"(b1));
            }
        }

        // ---- fused s1 accumulation (free: fragments are live) ----
        #pragma unroll
        for (int nt = 0; nt < 8; nt++) {
            s1[nt][0] += cacc[nt][0]; s1[nt][1] += cacc[nt][1];
            s1[nt][2] += cacc[nt][2]; s1[nt][3] += cacc[nt][3];
        }

        // ---- epilogue: fragments -> Osm rows 16wp..16wp+15 (own-warp rows only) ----
        {
            int r0 = 16 * wp + lr, r1 = r0 + 8;
            #pragma unroll
            for (int nt = 0; nt < 8; nt++) {
                int col = 8 * nt + 2 * lc;
                *(__half2*)&Osm[r0 * OPH2 + col] = __floats2half2_rn(cacc[nt][0], cacc[nt][1]);
                *(__half2*)&Osm[r1 * OPH2 + col] = __floats2half2_rn(cacc[nt][2], cacc[nt][3]);
            }
        }
        __syncwarp();

        // ---- store: 4 iters; per iter warp stores 4 rows x 128B contiguous ----
        #pragma unroll
        for (int r = 0; r < 4; r++) {
            int b = 16 * wp + 4 * r + rsub;
            uint4 v = *(uint4*)&Osm[b * OPH2 + colh];
            *(uint4*)(g_uhat + ((size_t)b * II + i) * (CC * DD) + 64 * e + colh) = v;
        }
        __syncthreads();   // mma/Osm reads done before next fill/epilogue
    }

    // ---- flush s1 partials (scale 1/32), full 32B sectors ----
    {
        float* dst = g_spart1[chunk];
        #pragma unroll
        for (int nt = 0; nt < 8; nt++) {
            int col = 64 * e + 8 * nt + 2 * lc;
            #pragma unroll
            for (int rp = 0; rp < 2; rp++) {
                int rowg = 16 * wp + lr + 8 * rp;
                float2 v2 = make_float2(s1[nt][rp * 2] * (1.0f / 32.0f),
                                        s1[nt][rp * 2 + 1] * (1.0f / 32.0f));
                *(float2*)&dst[rowg * 512 + col] = v2;
            }
        }
    }
}

// ---------- s1 reduce stage 1: 128 chunks -> 8 partials ----------
__global__ void reduce_stage1() {
    int gid = blockIdx.x * blockDim.x + threadIdx.x;   // 0..262143
    int g = gid >> 15, t = gid & 32767;
    float s = 0.0f;
    #pragma unroll
    for (int ch = 0; ch < NCH1 / 8; ch++)
        s += g_spart1[g * (NCH1 / 8) + ch][t];
    g_spart3[g][t] = s;
}

// ---------- s1 reduce stage 2 + squash -> g_V = v1 ----------
__global__ void reduce_stage2() {
    int t = blockIdx.x * blockDim.x + threadIdx.x;     // [b][n], n fastest
    float s = 0.0f;
    #pragma unroll
    for (int g = 0; g < 8; g++) s += g_spart3[g][t];

    float sq = s * s;
    #pragma unroll
    for (int off = 1; off < 16; off <<= 1)
        sq += __shfl_xor_sync(0xffffffffu, sq, off);   // capsule's 16 D's

    float f = 1.0f / ((1.0f + sq) * sqrtf(sq + 1e-9f));
    g_V[t] = s * f;
}

// ---------- routing pass (always full softmax vs V) ----------
__global__ __launch_bounds__(256) void routing_kernel() {
    const int b     = blockIdx.y;
    const int chunk = blockIdx.x;
    const int warp  = threadIdx.x >> 5;
    const int c     = threadIdx.x & 31;

    float V[DD];
    #pragma unroll
    for (int D = 0; D < DD; D++) V[D] = g_V[(b * CC + c) * DD + D];

    float sacc[DD];
    #pragma unroll
    for (int D = 0; D < DD; D++) sacc[D] = 0.0f;

    const int i0 = chunk * (8 * RITERS) + warp * RITERS;
    const uint4* p = (const uint4*)(g_uhat + ((size_t)b * II + i0) * (CC * DD)) + c * 2;

    uint4 q0 = p[0];
    uint4 q1 = p[1];

    #pragma unroll 4
    for (int k = 0; k < RITERS; k++) {
        uint4 n0 = q0, n1 = q1;
        if (k + 1 < RITERS) {
            n0 = p[(k + 1) * 64];
            n1 = p[(k + 1) * 64 + 1];
        }

        float u[DD];
        unsigned rr[8] = {q0.x, q0.y, q0.z, q0.w, q1.x, q1.y, q1.z, q1.w};
        #pragma unroll
        for (int pp = 0; pp < 8; pp++) {
            __half2 h = *reinterpret_cast<__half2*>(&rr[pp]);
            float2 f = __half22float2(h);
            u[2 * pp]     = f.x;
            u[2 * pp + 1] = f.y;
        }

        float logit = 0.0f;
        #pragma unroll
        for (int D = 0; D < DD; D++) logit = fmaf(u[D], V[D], logit);
        float m = logit;
        #pragma unroll
        for (int off = 16; off > 0; off >>= 1)
            m = fmaxf(m, __shfl_xor_sync(0xffffffffu, m, off));
        float ev = __expf(logit - m);
        float ssum = ev;
        #pragma unroll
        for (int off = 16; off > 0; off >>= 1)
            ssum += __shfl_xor_sync(0xffffffffu, ssum, off);
        float cij = ev / ssum;

        #pragma unroll
        for (int D = 0; D < DD; D++) sacc[D] = fmaf(cij, u[D], sacc[D]);

        q0 = n0; q1 = n1;
    }

    __shared__ float red[8][CC * DD];
    #pragma unroll
    for (int D = 0; D < DD; D++) red[warp][D * 32 + c] = sacc[D];
    __syncthreads();

    for (int t = threadIdx.x; t < CC * DD; t += 256) {
        float v = 0.0f;
        #pragma unroll
        for (int wq = 0; wq < 8; wq++) v += red[wq][t];
        g_spart[chunk][b * (CC * DD) + t] = v;   // [chunk][b][D][c]
    }
}

// ---------- squash (routing partials): pass 1 -> g_V += v2; pass 2 -> out = v3 ----
__global__ void squash_kernel(float* __restrict__ out, int pass) {
    int t = blockIdx.x * blockDim.x + threadIdx.x;   // (b,c,D), D fastest
    int bc = t >> 4, D = t & 15;
    int b = bc >> 5, c = bc & 31;
    int addr = b * (CC * DD) + D * 32 + c;           // [b][D][c] partial layout

    float s = 0.0f;
    #pragma unroll
    for (int ch = 0; ch < NCHUNK; ch++) s += g_spart[ch][addr];

    float sq = s * s;
    #pragma unroll
    for (int off = 1; off < 16; off <<= 1)
        sq += __shfl_xor_sync(0xffffffffu, sq, off);

    float f = 1.0f / ((1.0f + sq) * sqrtf(sq + 1e-9f));
    float v = s * f;

    if (pass == 1) g_V[t] += v;
    else           out[t] = v;
}

extern "C" void kernel_launch(void* const* d_in, const int* in_sizes, int n_in,
                              void* d_out, int out_size) {
    const float* x = (const float*)d_in[0];
    const float* w = (const float*)d_in[1];
    float* out = (float*)d_out;

    uhat_kernel<<<NCH1 * 8, 128>>>(x, w);       // u_hat + fused s1 partials
    reduce_stage1<<<1024, 256>>>();
    reduce_stage2<<<128, 256>>>();              // g_V = v1

    routing_kernel<<<dim3(NCHUNK, BB), 256>>>();  // pass 2
    squash_kernel<<<128, 256>>>(out, 1);          // g_V += v2

    routing_kernel<<<dim3(NCHUNK, BB), 256>>>();  // pass 3
    squash_kernel<<<128, 256>>>(out, 2);          // out = v3
}